// round 1
// baseline (speedup 1.0000x reference)
#include <cuda_runtime.h>
#include <cuda_bf16.h>
#include <cstdint>

// Problem constants (match reference)
#define NNODES 40000
#define FEAT   128
#define TM     16          // nodes per GEMM block

// Scratch (no allocations allowed — device globals)
__device__ float g_neigh_sum[(size_t)NNODES * FEAT];
__device__ float g_deg[NNODES];

// ---------------------------------------------------------------------------
// Kernel 1: zero the scratch buffers
// ---------------------------------------------------------------------------
__global__ void sage_zero_kernel() {
    const size_t total4 = ((size_t)NNODES * FEAT) / 4;   // float4 count for neigh_sum
    size_t i = (size_t)blockIdx.x * blockDim.x + threadIdx.x;
    size_t stride = (size_t)gridDim.x * blockDim.x;
    float4 z = make_float4(0.f, 0.f, 0.f, 0.f);
    float4* ns4 = reinterpret_cast<float4*>(g_neigh_sum);
    for (size_t p = i; p < total4; p += stride) ns4[p] = z;
    for (size_t p = i; p < NNODES; p += stride) g_deg[p] = 0.f;
}

// ---------------------------------------------------------------------------
// Kernel 2: edge scatter. One warp per edge.
//   lane l loads float4 #l of x[col[e]]  (128 floats = 32 float4)
//   red.global.add.v4.f32 into g_neigh_sum[row[e]]
//   lane 0 bumps degree.
// ---------------------------------------------------------------------------
__global__ void sage_scatter_kernel(const float* __restrict__ x,
                                    const int*   __restrict__ row,
                                    const int*   __restrict__ col,
                                    int E) {
    int gtid = blockIdx.x * blockDim.x + threadIdx.x;
    int e = gtid >> 5;
    if (e >= E) return;
    int lane = threadIdx.x & 31;

    int r = __ldg(&row[e]);
    int c = __ldg(&col[e]);

    const float4* src = reinterpret_cast<const float4*>(x + (size_t)c * FEAT);
    float4 v = __ldg(&src[lane]);

    float* dst = g_neigh_sum + (size_t)r * FEAT + lane * 4;
    asm volatile("red.global.add.v4.f32 [%0], {%1, %2, %3, %4};"
                 :: "l"(dst), "f"(v.x), "f"(v.y), "f"(v.z), "f"(v.w)
                 : "memory");

    if (lane == 0) {
        atomicAdd(&g_deg[r], 1.0f);   // no return value used -> RED
    }
}

// ---------------------------------------------------------------------------
// Kernel 3: out[n][j] = (neigh_sum[n][:]/ (deg[n]+eps)) . W[j][:] + b[j]
// blockDim = 128 (thread t owns output column j = t), TM nodes per block.
// W staged in smem with row stride 132 floats (+4 pad) -> conflict-free
// LDS.128 for both the staging stores and the mainloop loads.
// Means staged as float4 [TM][32], read via broadcast.
// ---------------------------------------------------------------------------
__global__ void __launch_bounds__(128)
sage_gemm_kernel(const float* __restrict__ W,
                 const float* __restrict__ b,
                 float*       __restrict__ out) {
    __shared__ float  Ws[FEAT * 132];        // 128 rows x 132 floats = 67.6 KB
    __shared__ float4 Ms[TM * 32];           // TM nodes x 32 float4   =  8  KB

    const int t = threadIdx.x;               // 0..127 == output column j
    const int node0 = blockIdx.x * TM;

    // Stage W (row-major [j][k]) into padded smem.
    const float4* W4 = reinterpret_cast<const float4*>(W);
#pragma unroll
    for (int i = 0; i < 32; i++) {
        int p  = t + i * 128;                // float4 index into W
        int j  = p >> 5;
        int k4 = p & 31;
        float4 v = __ldg(&W4[p]);
        *reinterpret_cast<float4*>(&Ws[j * 132 + k4 * 4]) = v;
    }

    // Stage means: neigh_sum / (deg + eps)
    const float4* ns4 = reinterpret_cast<const float4*>(g_neigh_sum + (size_t)node0 * FEAT);
#pragma unroll
    for (int i = 0; i < (TM * 32) / 128; i++) {
        int p  = t + i * 128;
        int m  = p >> 5;
        int k4 = p & 31;
        float4 v = __ldg(&ns4[p]);
        float inv = 1.0f / (g_deg[node0 + m] + 1e-6f);
        v.x *= inv; v.y *= inv; v.z *= inv; v.w *= inv;
        Ms[m * 32 + k4] = v;
    }
    __syncthreads();

    float acc[TM];
    const float bj = __ldg(&b[t]);
#pragma unroll
    for (int m = 0; m < TM; m++) acc[m] = bj;

#pragma unroll
    for (int k4 = 0; k4 < 32; k4++) {
        float4 w = *reinterpret_cast<const float4*>(&Ws[t * 132 + k4 * 4]);
#pragma unroll
        for (int m = 0; m < TM; m++) {
            float4 mv = Ms[m * 32 + k4];
            acc[m] = fmaf(w.x, mv.x, acc[m]);
            acc[m] = fmaf(w.y, mv.y, acc[m]);
            acc[m] = fmaf(w.z, mv.z, acc[m]);
            acc[m] = fmaf(w.w, mv.w, acc[m]);
        }
    }

#pragma unroll
    for (int m = 0; m < TM; m++) {
        out[(size_t)(node0 + m) * FEAT + t] = acc[m];
    }
}

// ---------------------------------------------------------------------------
// Launch
// ---------------------------------------------------------------------------
extern "C" void kernel_launch(void* const* d_in, const int* in_sizes, int n_in,
                              void* d_out, int out_size) {
    const float* x   = (const float*)d_in[0];
    const int*   row = (const int*)  d_in[1];
    const int*   col = (const int*)  d_in[2];
    const float* W   = (const float*)d_in[3];
    const float* b   = (const float*)d_in[4];
    float*       out = (float*)d_out;

    const int E = in_sizes[1];

    // 1) zero scratch
    sage_zero_kernel<<<2048, 256>>>();

    // 2) edge scatter: one warp per edge
    int warps_needed = E;
    int blocks = (warps_needed * 32 + 255) / 256;
    sage_scatter_kernel<<<blocks, 256>>>(x, row, col, E);

    // 3) mean + GEMM + bias
    sage_gemm_kernel<<<NNODES / TM, 128>>>(W, b, out);
}